// round 13
// baseline (speedup 1.0000x reference)
#include <cuda_runtime.h>
#include <cuda_bf16.h>
#include <cstdint>

#define N_NODES 100000
#define N_EDGES 640000
#define D 128
#define TILE_M 128
#define CTA_M 256                       // two stages of TILE_M per CTA
#define NTILES2 ((N_NODES + CTA_M - 1) / CTA_M)
#define SCAN_B 98                       // ceil(100000/1024)

// ---------------- scratch (device globals; no dynamic allocation) ----------
__device__ float g_conv[N_NODES * D];   // (nodes@W2 + b2) * rsqrt(send_deg)
__device__ float g_gvec[D];             // globals@W3 + b3 + b1  (folded)
__device__ float g_an[D];               // column sum of h
__device__ int   g_cnt_s[N_NODES];      // send degree (int)
__device__ int   g_cnt_r[N_NODES];      // recv degree (int)
__device__ int   g_rowstart[N_NODES + 1];
__device__ int   g_cursor[N_NODES];
__device__ int   g_bsum[128];
__device__ int   g_csr[N_EDGES];        // sender ids bucketed by receiver
// weight images, transposed to [n][k], bf16 hi/lo, XOR-swizzled: W1h,W1l,W2h,W2l
__device__ __align__(16) unsigned char g_Wimg[4 * 32768];

// swizzled byte offset of element (row, k) in a 128x128 bf16 image (256B rows)
__device__ __forceinline__ uint32_t swz_off(int row, int k) {
    return (uint32_t)row * 256u + (((uint32_t)k * 2u) ^ (((uint32_t)row & 7u) * 16u));
}
__device__ __forceinline__ uint32_t smem_u32(const void* p) {
    uint32_t a;
    asm("{ .reg .u64 t; cvta.to.shared.u64 t, %1; cvt.u32.u64 %0, t; }" : "=r"(a) : "l"(p));
    return a;
}
__device__ __forceinline__ void ldsm4(uint32_t& r0, uint32_t& r1, uint32_t& r2,
                                      uint32_t& r3, uint32_t addr) {
    asm volatile("ldmatrix.sync.aligned.m8n8.x4.shared.b16 {%0,%1,%2,%3}, [%4];"
                 : "=r"(r0), "=r"(r1), "=r"(r2), "=r"(r3) : "r"(addr));
}
__device__ __forceinline__ void mma16816(float* c, const uint32_t* a,
                                         const uint32_t* b) {
    asm volatile(
        "mma.sync.aligned.m16n8k16.row.col.f32.bf16.bf16.f32 "
        "{%0,%1,%2,%3}, {%4,%5,%6,%7}, {%8,%9}, {%0,%1,%2,%3};"
        : "+f"(c[0]), "+f"(c[1]), "+f"(c[2]), "+f"(c[3])
        : "r"(a[0]), "r"(a[1]), "r"(a[2]), "r"(a[3]), "r"(b[0]), "r"(b[1]));
}

// ---------------- fused prep: weight split + gvec + zeroing -----------------
// blocks 0..127:   weight split/transpose (W1/W2 -> bf16 hi/lo images)
// blocks 128..143: gvec (8 warps = 8 cols each) + g_an zero (block 128)
// blocks 144..:    zero g_cnt_s / g_cnt_r
__global__ __launch_bounds__(256)
void prep_kernel(const float* __restrict__ W1, const float* __restrict__ W2,
                 const float* __restrict__ g,  const float* __restrict__ W3,
                 const float* __restrict__ b3, const float* __restrict__ b1) {
    int bx = blockIdx.x, tid = threadIdx.x;
    if (bx < 128) {
        int mat = bx & 1;                     // 0: W1, 1: W2
        int idx = (bx >> 1) * 256 + tid;      // 0..16383
        const float* W = mat ? W2 : W1;
        unsigned char* hi = g_Wimg + (size_t)(mat * 2) * 32768;
        unsigned char* lo = hi + 32768;
        int k = idx >> 7, n = idx & 127;      // coalesced read of W[k][n]
        float w = W[k * D + n];
        __nv_bfloat16 h = __float2bfloat16_rn(w);
        __nv_bfloat16 l = __float2bfloat16_rn(w - __bfloat162float(h));
        uint32_t off = swz_off(n, k);
        *(__nv_bfloat16*)(hi + off) = h;
        *(__nv_bfloat16*)(lo + off) = l;
    } else if (bx < 144) {
        if (bx == 128 && tid < D) g_an[tid] = 0.f;
        int w = tid >> 5, lane = tid & 31;
        int c = (bx - 128) * 8 + w;
        float s = 0.f;
#pragma unroll
        for (int k = lane; k < D; k += 32) s += g[k] * W3[k * D + c];
#pragma unroll
        for (int o = 16; o; o >>= 1) s += __shfl_xor_sync(0xffffffffu, s, o);
        if (lane == 0) g_gvec[c] = s + b3[c] + b1[c];
    } else {
        int i = (bx - 144) * 256 + tid;
        if (i < N_NODES) { g_cnt_s[i] = 0; g_cnt_r[i] = 0; }
    }
}

__global__ void degree_kernel(const int* __restrict__ senders,
                              const int* __restrict__ receivers) {
    int e = blockIdx.x * blockDim.x + threadIdx.x;
    if (e < N_EDGES) {
        atomicAdd(&g_cnt_s[senders[e]], 1);
        atomicAdd(&g_cnt_r[receivers[e]], 1);
    }
}

// ---------------- exclusive scan of recv counts -> g_rowstart ---------------
__global__ __launch_bounds__(1024) void scan1_kernel() {
    __shared__ int wsum[32];
    int t = threadIdx.x, i = blockIdx.x * 1024 + t;
    int lane = t & 31, w = t >> 5;
    int v = (i < N_NODES) ? g_cnt_r[i] : 0;
    int x = v;
#pragma unroll
    for (int off = 1; off < 32; off <<= 1) {
        int y = __shfl_up_sync(0xffffffffu, x, off);
        if (lane >= off) x += y;
    }
    if (lane == 31) wsum[w] = x;
    __syncthreads();
    if (w == 0) {
        int s = wsum[lane];
#pragma unroll
        for (int off = 1; off < 32; off <<= 1) {
            int y = __shfl_up_sync(0xffffffffu, s, off);
            if (lane >= off) s += y;
        }
        wsum[lane] = s;
    }
    __syncthreads();
    int incl = x + (w > 0 ? wsum[w - 1] : 0);
    if (i < N_NODES) g_rowstart[i] = incl - v;
    if (t == 1023) g_bsum[blockIdx.x] = incl;
}
// scan3 computes its own cross-block offset by reducing g_bsum[0..bx) in-block
__global__ __launch_bounds__(1024) void scan3_kernel() {
    __shared__ int ws[32];
    int t = threadIdx.x, bx = blockIdx.x;
    int lane = t & 31, w = t >> 5;
    int v = (t < bx) ? g_bsum[t] : 0;        // bx <= 97 so one pass suffices
#pragma unroll
    for (int o = 16; o; o >>= 1) v += __shfl_xor_sync(0xffffffffu, v, o);
    if (lane == 0) ws[w] = v;
    __syncthreads();
    if (t < 32) {
        int s = ws[t];
#pragma unroll
        for (int o = 16; o; o >>= 1) s += __shfl_xor_sync(0xffffffffu, s, o);
        if (t == 0) ws[0] = s;
    }
    __syncthreads();
    int base = ws[0];
    int i = bx * 1024 + t;
    if (i < N_NODES) {
        int val = g_rowstart[i] + base;
        g_rowstart[i] = val;
        g_cursor[i] = val;
    }
    if (i == N_NODES) g_rowstart[N_NODES] = N_EDGES;
}
__global__ void bucket_kernel(const int* __restrict__ senders,
                              const int* __restrict__ receivers) {
    int e = blockIdx.x * blockDim.x + threadIdx.x;
    if (e < N_EDGES) {
        int pos = atomicAdd(&g_cursor[receivers[e]], 1);
        g_csr[pos] = senders[e];
    }
}

// ---------------- HMMA dual GEMM (512 threads, 16 warps, 2 row-tiles) -------
#define SM_AHI  0
#define SM_ALO  32768
#define SM_W    65536                       // W1h,W1l,W2h,W2l (131072 B)
#define SM_BIAS (SM_W + 4 * 32768)          // 256 floats: gvec | b2
#define SM_DEG  (SM_BIAS + 1024)            // 256 floats (rsqrt send deg)
#define SM_TOTAL (SM_DEG + 1024)
#define GT 512

__global__ __launch_bounds__(GT, 1)
void gemm_hmma_kernel(const float* __restrict__ nodes,
                      const float* __restrict__ b2,
                      float* __restrict__ out) {
    extern __shared__ unsigned char smem[];
    uint32_t sbase = smem_u32(smem);
    int tid = threadIdx.x, wid = tid >> 5, lane = tid & 31;
    int row0 = blockIdx.x * CTA_M;
    float* sbias = (float*)(smem + SM_BIAS);
    float* sdeg  = (float*)(smem + SM_DEG);

    // ---- once-per-CTA prologue: biases, degs, weight images (plain float4)
    if (tid < D) {
        sbias[tid] = g_gvec[tid];
        sbias[D + tid] = b2[tid];
    }
    if (tid < CTA_M) {
        int gr = row0 + tid;
        sdeg[tid] = (gr < N_NODES) ? rsqrtf(fmaxf((float)g_cnt_s[gr], 1.f)) : 0.f;
    }
    {
        const float4* src = (const float4*)g_Wimg;
        float4* dst = (float4*)(smem + SM_W);
#pragma unroll
        for (int i = tid; i < (4 * 32768) / 16; i += GT) dst[i] = src[i];
    }

    // warp-constant addressing (identical math to the r9 passing kernel)
    int g = lane >> 3, i8 = lane & 7;
    int rA = i8 + 8 * (g & 1);
    int rB = i8 + 8 * (g >> 1);
    int wm = (wid & 3) * 32;
    int wc = wid >> 2;
    bool isW2 = wc >= 2;
    int wn = (wc & 1) * 64;
    uint32_t aHI = sbase + SM_AHI, aLO = sbase + SM_ALO;
    uint32_t wH = sbase + SM_W + (isW2 ? 2 : 0) * 32768;
    uint32_t wL = wH + 32768;
    uint32_t swzA = (uint32_t)i8 * 16u;
    int groupr = lane >> 2, qc = lane & 3;

#pragma unroll 1
    for (int st = 0; st < 2; st++) {
        int rbase = row0 + st * TILE_M;
        if (rbase >= N_NODES) break;
        // ---- stage A convert: fp32 -> bf16 hi/lo, swizzled ----------------
        {
            const float4* n4 = (const float4*)nodes;
#pragma unroll
            for (int i = tid; i < TILE_M * (D / 4); i += GT) {
                int r = i >> 5, q = i & 31;
                int gr = rbase + r;
                float4 v = (gr < N_NODES) ? n4[(size_t)gr * (D / 4) + q]
                                          : make_float4(0.f, 0.f, 0.f, 0.f);
                __nv_bfloat16 h0 = __float2bfloat16_rn(v.x), h1 = __float2bfloat16_rn(v.y);
                __nv_bfloat16 h2 = __float2bfloat16_rn(v.z), h3 = __float2bfloat16_rn(v.w);
                __nv_bfloat16 l0 = __float2bfloat16_rn(v.x - __bfloat162float(h0));
                __nv_bfloat16 l1 = __float2bfloat16_rn(v.y - __bfloat162float(h1));
                __nv_bfloat16 l2 = __float2bfloat16_rn(v.z - __bfloat162float(h2));
                __nv_bfloat16 l3 = __float2bfloat16_rn(v.w - __bfloat162float(h3));
                uint32_t off = (uint32_t)r * 256u +
                               (((uint32_t)q * 8u) ^ (((uint32_t)r & 7u) * 16u));
                __nv_bfloat162 ph0{h0, h1}, ph1{h2, h3}, pl0{l0, l1}, pl1{l2, l3};
                uint2 uh{*(uint32_t*)&ph0, *(uint32_t*)&ph1};
                uint2 ul{*(uint32_t*)&pl0, *(uint32_t*)&pl1};
                *(uint2*)(smem + SM_AHI + off) = uh;
                *(uint2*)(smem + SM_ALO + off) = ul;
            }
        }
        __syncthreads();

        // ---- mainloop ------------------------------------------------------
        float c[2][8][4];
#pragma unroll
        for (int mi = 0; mi < 2; mi++)
#pragma unroll
            for (int ni = 0; ni < 8; ni++)
#pragma unroll
                for (int q = 0; q < 4; q++) c[mi][ni][q] = 0.f;

#pragma unroll
        for (int ks = 0; ks < 8; ks++) {
            uint32_t kA = ((uint32_t)(ks * 32 + (g >> 1) * 16)) ^ swzA;
            uint32_t kB = ((uint32_t)(ks * 32 + (g & 1) * 16)) ^ swzA;
            uint32_t bh[8][2], bl[8][2];
#pragma unroll
            for (int nt = 0; nt < 4; nt++) {
                uint32_t rowoff = (uint32_t)(wn + nt * 16 + rB) * 256u;
                ldsm4(bh[nt * 2][0], bh[nt * 2][1], bh[nt * 2 + 1][0], bh[nt * 2 + 1][1],
                      wH + rowoff + kB);
                ldsm4(bl[nt * 2][0], bl[nt * 2][1], bl[nt * 2 + 1][0], bl[nt * 2 + 1][1],
                      wL + rowoff + kB);
            }
            uint32_t a[2][4];
#pragma unroll
            for (int mi = 0; mi < 2; mi++)
                ldsm4(a[mi][0], a[mi][1], a[mi][2], a[mi][3],
                      aHI + (uint32_t)(wm + mi * 16 + rA) * 256u + kA);
#pragma unroll
            for (int mi = 0; mi < 2; mi++)
#pragma unroll
                for (int ni = 0; ni < 8; ni++) {
                    mma16816(c[mi][ni], a[mi], bh[ni]);
                    mma16816(c[mi][ni], a[mi], bl[ni]);
                }
#pragma unroll
            for (int mi = 0; mi < 2; mi++)
                ldsm4(a[mi][0], a[mi][1], a[mi][2], a[mi][3],
                      aLO + (uint32_t)(wm + mi * 16 + rA) * 256u + kA);
#pragma unroll
            for (int mi = 0; mi < 2; mi++)
#pragma unroll
                for (int ni = 0; ni < 8; ni++)
                    mma16816(c[mi][ni], a[mi], bh[ni]);
        }

        // ---- stage epilogue ------------------------------------------------
#pragma unroll
        for (int mi = 0; mi < 2; mi++) {
            int r1 = wm + mi * 16 + groupr, r2 = r1 + 8;
            int gr1 = rbase + r1, gr2 = rbase + r2;
            float rv1 = sdeg[st * TILE_M + r1], rv2 = sdeg[st * TILE_M + r2];
#pragma unroll
            for (int ni = 0; ni < 8; ni++) {
                int cc = wn + ni * 8 + qc * 2;
                float* acc = c[mi][ni];
                if (!isW2) {
                    float2 v1{acc[0] + sbias[cc], acc[1] + sbias[cc + 1]};
                    float2 v2{acc[2] + sbias[cc], acc[3] + sbias[cc + 1]};
                    if (gr1 < N_NODES) *(float2*)&out[(size_t)gr1 * D + cc] = v1;
                    if (gr2 < N_NODES) *(float2*)&out[(size_t)gr2 * D + cc] = v2;
                } else {
                    float2 v1{(acc[0] + sbias[D + cc]) * rv1,
                              (acc[1] + sbias[D + cc + 1]) * rv1};
                    float2 v2{(acc[2] + sbias[D + cc]) * rv2,
                              (acc[3] + sbias[D + cc + 1]) * rv2};
                    if (gr1 < N_NODES) *(float2*)&g_conv[(size_t)gr1 * D + cc] = v1;
                    if (gr2 < N_NODES) *(float2*)&g_conv[(size_t)gr2 * D + cc] = v2;
                }
            }
        }
        __syncthreads();   // A smem reused next stage
    }
}

// ---------------- fused aggregate + finalize --------------------------------
// warp per node (8 nodes/warp): agg = sum conv[s]; h = relu(h1 + agg*rr) + nodes
// also accumulates column sum of h into g_an. 4-way gather unroll for MLP.
#define ANB 64                       // nodes per block (8 warps x 8 nodes)
__global__ __launch_bounds__(256)
void aggregate_kernel(const float* __restrict__ nodes,
                      float* __restrict__ out) {
    __shared__ float scol[D];
    int tid = threadIdx.x, w = tid >> 5, lane = tid & 31;
    if (tid < D) scol[tid] = 0.f;
    __syncthreads();

    float4 col = make_float4(0.f, 0.f, 0.f, 0.f);
#pragma unroll 1
    for (int j = 0; j < 8; j++) {
        int node = blockIdx.x * ANB + w * 8 + j;
        if (node >= N_NODES) break;
        int e0 = g_rowstart[node], e1 = g_rowstart[node + 1];
        float4 a0 = make_float4(0.f, 0.f, 0.f, 0.f);
        float4 a1 = make_float4(0.f, 0.f, 0.f, 0.f);
        float4 a2 = make_float4(0.f, 0.f, 0.f, 0.f);
        float4 a3 = make_float4(0.f, 0.f, 0.f, 0.f);
        int e = e0;
        for (; e + 3 < e1; e += 4) {
            int s0 = __ldg(&g_csr[e]);
            int s1 = __ldg(&g_csr[e + 1]);
            int s2 = __ldg(&g_csr[e + 2]);
            int s3 = __ldg(&g_csr[e + 3]);
            float4 v0 = *(const float4*)&g_conv[(size_t)s0 * D + lane * 4];
            float4 v1 = *(const float4*)&g_conv[(size_t)s1 * D + lane * 4];
            float4 v2 = *(const float4*)&g_conv[(size_t)s2 * D + lane * 4];
            float4 v3 = *(const float4*)&g_conv[(size_t)s3 * D + lane * 4];
            a0.x += v0.x; a0.y += v0.y; a0.z += v0.z; a0.w += v0.w;
            a1.x += v1.x; a1.y += v1.y; a1.z += v1.z; a1.w += v1.w;
            a2.x += v2.x; a2.y += v2.y; a2.z += v2.z; a2.w += v2.w;
            a3.x += v3.x; a3.y += v3.y; a3.z += v3.z; a3.w += v3.w;
        }
        for (; e < e1; e++) {
            int s0 = __ldg(&g_csr[e]);
            float4 v0 = *(const float4*)&g_conv[(size_t)s0 * D + lane * 4];
            a0.x += v0.x; a0.y += v0.y; a0.z += v0.z; a0.w += v0.w;
        }
        a0.x += a1.x + a2.x + a3.x;
        a0.y += a1.y + a2.y + a3.y;
        a0.z += a1.z + a2.z + a3.z;
        a0.w += a1.w + a2.w + a3.w;
        float rr = rsqrtf(fmaxf((float)(e1 - e0), 1.f));
        size_t idx = (size_t)node * D + lane * 4;
        float4 h1 = *(const float4*)&out[idx];
        float4 nd = *(const float4*)&nodes[idx];
        float4 h;
        h.x = fmaxf(h1.x + a0.x * rr, 0.f) + nd.x;
        h.y = fmaxf(h1.y + a0.y * rr, 0.f) + nd.y;
        h.z = fmaxf(h1.z + a0.z * rr, 0.f) + nd.z;
        h.w = fmaxf(h1.w + a0.w * rr, 0.f) + nd.w;
        *(float4*)&out[idx] = h;
        col.x += h.x; col.y += h.y; col.z += h.z; col.w += h.w;
    }
    atomicAdd(&scol[lane * 4 + 0], col.x);
    atomicAdd(&scol[lane * 4 + 1], col.y);
    atomicAdd(&scol[lane * 4 + 2], col.z);
    atomicAdd(&scol[lane * 4 + 3], col.w);
    __syncthreads();
    if (tid < D) atomicAdd(&g_an[tid], scol[tid]);
}

// ---------------- global update: g_new = g + relu([an; g] @ Wg + bg) -------
__global__ void gnew_kernel(const float* __restrict__ g,
                            const float* __restrict__ Wg,
                            const float* __restrict__ bg,
                            float* __restrict__ out2) {
    __shared__ float sv[2 * D];
    int c = threadIdx.x;
    sv[c] = g_an[c];
    sv[D + c] = g[c];
    __syncthreads();
    float acc = bg[c];
#pragma unroll 8
    for (int k = 0; k < 2 * D; k++) acc += sv[k] * Wg[k * D + c];
    out2[c] = g[c] + fmaxf(acc, 0.f);
}

// ---------------- launch ----------------------------------------------------
extern "C" void kernel_launch(void* const* d_in, const int* in_sizes, int n_in,
                              void* d_out, int out_size) {
    const float* nodes    = (const float*)d_in[0];
    const float* globals_ = (const float*)d_in[1];
    const int*   senders   = (const int*)d_in[2];
    const int*   receivers = (const int*)d_in[3];
    const float* W1w = (const float*)d_in[4];
    const float* W1b = (const float*)d_in[5];
    const float* W2w = (const float*)d_in[6];
    const float* W2b = (const float*)d_in[7];
    const float* W3w = (const float*)d_in[8];
    const float* W3b = (const float*)d_in[9];
    const float* Wgw = (const float*)d_in[10];
    const float* Wgb = (const float*)d_in[11];
    float* out = (float*)d_out;

    cudaFuncSetAttribute(gemm_hmma_kernel, cudaFuncAttributeMaxDynamicSharedMemorySize,
                         SM_TOTAL);

    prep_kernel<<<144 + (N_NODES + 255) / 256, 256>>>(W1w, W2w, globals_, W3w, W3b, W1b);
    degree_kernel<<<(N_EDGES + 255) / 256, 256>>>(senders, receivers);
    scan1_kernel<<<SCAN_B, 1024>>>();
    scan3_kernel<<<SCAN_B, 1024>>>();
    bucket_kernel<<<(N_EDGES + 255) / 256, 256>>>(senders, receivers);
    gemm_hmma_kernel<<<NTILES2, GT, SM_TOTAL>>>(nodes, W2b, out);
    aggregate_kernel<<<(N_NODES + ANB - 1) / ANB, 256>>>(nodes, out);
    gnew_kernel<<<1, 128>>>(globals_, Wgw, Wgb, out + (size_t)N_NODES * D);
}

// round 14
// speedup vs baseline: 1.0678x; 1.0678x over previous
#include <cuda_runtime.h>
#include <cuda_bf16.h>
#include <cstdint>

#define N_NODES 100000
#define N_EDGES 640000
#define D 128
#define TILE_M 128
#define CTA_M 256                       // two stages of TILE_M per CTA
#define NTILES2 ((N_NODES + CTA_M - 1) / CTA_M)
#define SCAN_B 98                       // ceil(100000/1024)

// ---------------- scratch (device globals; no dynamic allocation) ----------
__device__ float g_conv[N_NODES * D];   // (nodes@W2 + b2) * rsqrt(send_deg)
__device__ float g_gvec[D];             // globals@W3 + b3 + b1  (folded)
__device__ float g_an[D];               // column sum of h
__device__ int   g_cnt_s[N_NODES];      // send degree (int)
__device__ int   g_cnt_r[N_NODES];      // recv degree (int)
__device__ int   g_rowstart[N_NODES + 1];
__device__ int   g_cursor[N_NODES];
__device__ int   g_bsum[128];
__device__ int   g_done;                // aggregate block-completion counter
__device__ int   g_csr[N_EDGES];        // sender ids bucketed by receiver
// weight images, transposed to [n][k], bf16 hi/lo, XOR-swizzled: W1h,W1l,W2h,W2l
__device__ __align__(16) unsigned char g_Wimg[4 * 32768];

// swizzled byte offset of element (row, k) in a 128x128 bf16 image (256B rows)
__device__ __forceinline__ uint32_t swz_off(int row, int k) {
    return (uint32_t)row * 256u + (((uint32_t)k * 2u) ^ (((uint32_t)row & 7u) * 16u));
}
__device__ __forceinline__ uint32_t smem_u32(const void* p) {
    uint32_t a;
    asm("{ .reg .u64 t; cvta.to.shared.u64 t, %1; cvt.u32.u64 %0, t; }" : "=r"(a) : "l"(p));
    return a;
}
__device__ __forceinline__ void ldsm4(uint32_t& r0, uint32_t& r1, uint32_t& r2,
                                      uint32_t& r3, uint32_t addr) {
    asm volatile("ldmatrix.sync.aligned.m8n8.x4.shared.b16 {%0,%1,%2,%3}, [%4];"
                 : "=r"(r0), "=r"(r1), "=r"(r2), "=r"(r3) : "r"(addr));
}
__device__ __forceinline__ void mma16816(float* c, const uint32_t* a,
                                         const uint32_t* b) {
    asm volatile(
        "mma.sync.aligned.m16n8k16.row.col.f32.bf16.bf16.f32 "
        "{%0,%1,%2,%3}, {%4,%5,%6,%7}, {%8,%9}, {%0,%1,%2,%3};"
        : "+f"(c[0]), "+f"(c[1]), "+f"(c[2]), "+f"(c[3])
        : "r"(a[0]), "r"(a[1]), "r"(a[2]), "r"(a[3]), "r"(b[0]), "r"(b[1]));
}

// ---------------- fused prep: weight split + gvec + zeroing -----------------
// blocks 0..127:   weight split/transpose (W1/W2 -> bf16 hi/lo images)
// blocks 128..143: gvec (8 warps = 8 cols each) + g_an zero (block 128)
// blocks 144..:    zero g_cnt_s / g_cnt_r
__global__ __launch_bounds__(256)
void prep_kernel(const float* __restrict__ W1, const float* __restrict__ W2,
                 const float* __restrict__ g,  const float* __restrict__ W3,
                 const float* __restrict__ b3, const float* __restrict__ b1) {
    int bx = blockIdx.x, tid = threadIdx.x;
    if (bx < 128) {
        int mat = bx & 1;                     // 0: W1, 1: W2
        int idx = (bx >> 1) * 256 + tid;      // 0..16383
        const float* W = mat ? W2 : W1;
        unsigned char* hi = g_Wimg + (size_t)(mat * 2) * 32768;
        unsigned char* lo = hi + 32768;
        int k = idx >> 7, n = idx & 127;      // coalesced read of W[k][n]
        float w = W[k * D + n];
        __nv_bfloat16 h = __float2bfloat16_rn(w);
        __nv_bfloat16 l = __float2bfloat16_rn(w - __bfloat162float(h));
        uint32_t off = swz_off(n, k);
        *(__nv_bfloat16*)(hi + off) = h;
        *(__nv_bfloat16*)(lo + off) = l;
    } else if (bx < 144) {
        if (bx == 128 && tid < D) g_an[tid] = 0.f;
        if (bx == 128 && tid == 0) g_done = 0;
        int w = tid >> 5, lane = tid & 31;
        int c = (bx - 128) * 8 + w;
        float s = 0.f;
#pragma unroll
        for (int k = lane; k < D; k += 32) s += g[k] * W3[k * D + c];
#pragma unroll
        for (int o = 16; o; o >>= 1) s += __shfl_xor_sync(0xffffffffu, s, o);
        if (lane == 0) g_gvec[c] = s + b3[c] + b1[c];
    } else {
        int i = (bx - 144) * 256 + tid;
        if (i < N_NODES) { g_cnt_s[i] = 0; g_cnt_r[i] = 0; }
    }
}

__global__ void degree_kernel(const int* __restrict__ senders,
                              const int* __restrict__ receivers) {
    int e = blockIdx.x * blockDim.x + threadIdx.x;
    if (e < N_EDGES) {
        atomicAdd(&g_cnt_s[senders[e]], 1);
        atomicAdd(&g_cnt_r[receivers[e]], 1);
    }
}

// ---------------- exclusive scan of recv counts -> g_rowstart ---------------
__global__ __launch_bounds__(1024) void scan1_kernel() {
    __shared__ int wsum[32];
    int t = threadIdx.x, i = blockIdx.x * 1024 + t;
    int lane = t & 31, w = t >> 5;
    int v = (i < N_NODES) ? g_cnt_r[i] : 0;
    int x = v;
#pragma unroll
    for (int off = 1; off < 32; off <<= 1) {
        int y = __shfl_up_sync(0xffffffffu, x, off);
        if (lane >= off) x += y;
    }
    if (lane == 31) wsum[w] = x;
    __syncthreads();
    if (w == 0) {
        int s = wsum[lane];
#pragma unroll
        for (int off = 1; off < 32; off <<= 1) {
            int y = __shfl_up_sync(0xffffffffu, s, off);
            if (lane >= off) s += y;
        }
        wsum[lane] = s;
    }
    __syncthreads();
    int incl = x + (w > 0 ? wsum[w - 1] : 0);
    if (i < N_NODES) g_rowstart[i] = incl - v;
    if (t == 1023) g_bsum[blockIdx.x] = incl;
}
// scan3 computes its own cross-block offset by reducing g_bsum[0..bx) in-block
__global__ __launch_bounds__(1024) void scan3_kernel() {
    __shared__ int ws[32];
    int t = threadIdx.x, bx = blockIdx.x;
    int lane = t & 31, w = t >> 5;
    int v = (t < bx) ? g_bsum[t] : 0;        // bx <= 97 so one pass suffices
#pragma unroll
    for (int o = 16; o; o >>= 1) v += __shfl_xor_sync(0xffffffffu, v, o);
    if (lane == 0) ws[w] = v;
    __syncthreads();
    if (t < 32) {
        int s = ws[t];
#pragma unroll
        for (int o = 16; o; o >>= 1) s += __shfl_xor_sync(0xffffffffu, s, o);
        if (t == 0) ws[0] = s;
    }
    __syncthreads();
    int base = ws[0];
    int i = bx * 1024 + t;
    if (i < N_NODES) {
        int val = g_rowstart[i] + base;
        g_rowstart[i] = val;
        g_cursor[i] = val;
    }
    if (i == N_NODES) g_rowstart[N_NODES] = N_EDGES;
}
__global__ void bucket_kernel(const int* __restrict__ senders,
                              const int* __restrict__ receivers) {
    int e = blockIdx.x * blockDim.x + threadIdx.x;
    if (e < N_EDGES) {
        int pos = atomicAdd(&g_cursor[receivers[e]], 1);
        g_csr[pos] = senders[e];
    }
}

// ---------------- HMMA dual GEMM (512 threads, 16 warps, 2 row-tiles) -------
#define SM_AHI  0
#define SM_ALO  32768
#define SM_W    65536                       // W1h,W1l,W2h,W2l (131072 B)
#define SM_BIAS (SM_W + 4 * 32768)          // 256 floats: gvec | b2
#define SM_DEG  (SM_BIAS + 1024)            // 256 floats (rsqrt send deg)
#define SM_TOTAL (SM_DEG + 1024)
#define GT 512

__global__ __launch_bounds__(GT, 1)
void gemm_hmma_kernel(const float* __restrict__ nodes,
                      const float* __restrict__ b2,
                      float* __restrict__ out) {
    extern __shared__ unsigned char smem[];
    uint32_t sbase = smem_u32(smem);
    int tid = threadIdx.x, wid = tid >> 5, lane = tid & 31;
    int row0 = blockIdx.x * CTA_M;
    float* sbias = (float*)(smem + SM_BIAS);
    float* sdeg  = (float*)(smem + SM_DEG);

    // ---- once-per-CTA prologue: biases, degs, weight images (plain float4)
    if (tid < D) {
        sbias[tid] = g_gvec[tid];
        sbias[D + tid] = b2[tid];
    }
    if (tid < CTA_M) {
        int gr = row0 + tid;
        sdeg[tid] = (gr < N_NODES) ? rsqrtf(fmaxf((float)g_cnt_s[gr], 1.f)) : 0.f;
    }
    {
        const float4* src = (const float4*)g_Wimg;
        float4* dst = (float4*)(smem + SM_W);
#pragma unroll
        for (int i = tid; i < (4 * 32768) / 16; i += GT) dst[i] = src[i];
    }

    // warp-constant addressing (identical math to the r9 passing kernel)
    int g = lane >> 3, i8 = lane & 7;
    int rA = i8 + 8 * (g & 1);
    int rB = i8 + 8 * (g >> 1);
    int wm = (wid & 3) * 32;
    int wc = wid >> 2;
    bool isW2 = wc >= 2;
    int wn = (wc & 1) * 64;
    uint32_t aHI = sbase + SM_AHI, aLO = sbase + SM_ALO;
    uint32_t wH = sbase + SM_W + (isW2 ? 2 : 0) * 32768;
    uint32_t wL = wH + 32768;
    uint32_t swzA = (uint32_t)i8 * 16u;
    int groupr = lane >> 2, qc = lane & 3;

#pragma unroll 1
    for (int st = 0; st < 2; st++) {
        int rbase = row0 + st * TILE_M;
        if (rbase >= N_NODES) break;
        // ---- stage A convert: fp32 -> bf16 hi/lo, swizzled ----------------
        {
            const float4* n4 = (const float4*)nodes;
#pragma unroll
            for (int i = tid; i < TILE_M * (D / 4); i += GT) {
                int r = i >> 5, q = i & 31;
                int gr = rbase + r;
                float4 v = (gr < N_NODES) ? n4[(size_t)gr * (D / 4) + q]
                                          : make_float4(0.f, 0.f, 0.f, 0.f);
                __nv_bfloat16 h0 = __float2bfloat16_rn(v.x), h1 = __float2bfloat16_rn(v.y);
                __nv_bfloat16 h2 = __float2bfloat16_rn(v.z), h3 = __float2bfloat16_rn(v.w);
                __nv_bfloat16 l0 = __float2bfloat16_rn(v.x - __bfloat162float(h0));
                __nv_bfloat16 l1 = __float2bfloat16_rn(v.y - __bfloat162float(h1));
                __nv_bfloat16 l2 = __float2bfloat16_rn(v.z - __bfloat162float(h2));
                __nv_bfloat16 l3 = __float2bfloat16_rn(v.w - __bfloat162float(h3));
                uint32_t off = (uint32_t)r * 256u +
                               (((uint32_t)q * 8u) ^ (((uint32_t)r & 7u) * 16u));
                __nv_bfloat162 ph0{h0, h1}, ph1{h2, h3}, pl0{l0, l1}, pl1{l2, l3};
                uint2 uh{*(uint32_t*)&ph0, *(uint32_t*)&ph1};
                uint2 ul{*(uint32_t*)&pl0, *(uint32_t*)&pl1};
                *(uint2*)(smem + SM_AHI + off) = uh;
                *(uint2*)(smem + SM_ALO + off) = ul;
            }
        }
        __syncthreads();

        // ---- mainloop ------------------------------------------------------
        float c[2][8][4];
#pragma unroll
        for (int mi = 0; mi < 2; mi++)
#pragma unroll
            for (int ni = 0; ni < 8; ni++)
#pragma unroll
                for (int q = 0; q < 4; q++) c[mi][ni][q] = 0.f;

#pragma unroll
        for (int ks = 0; ks < 8; ks++) {
            uint32_t kA = ((uint32_t)(ks * 32 + (g >> 1) * 16)) ^ swzA;
            uint32_t kB = ((uint32_t)(ks * 32 + (g & 1) * 16)) ^ swzA;
            uint32_t bh[8][2], bl[8][2];
#pragma unroll
            for (int nt = 0; nt < 4; nt++) {
                uint32_t rowoff = (uint32_t)(wn + nt * 16 + rB) * 256u;
                ldsm4(bh[nt * 2][0], bh[nt * 2][1], bh[nt * 2 + 1][0], bh[nt * 2 + 1][1],
                      wH + rowoff + kB);
                ldsm4(bl[nt * 2][0], bl[nt * 2][1], bl[nt * 2 + 1][0], bl[nt * 2 + 1][1],
                      wL + rowoff + kB);
            }
            uint32_t a[2][4];
#pragma unroll
            for (int mi = 0; mi < 2; mi++)
                ldsm4(a[mi][0], a[mi][1], a[mi][2], a[mi][3],
                      aHI + (uint32_t)(wm + mi * 16 + rA) * 256u + kA);
#pragma unroll
            for (int mi = 0; mi < 2; mi++)
#pragma unroll
                for (int ni = 0; ni < 8; ni++) {
                    mma16816(c[mi][ni], a[mi], bh[ni]);
                    mma16816(c[mi][ni], a[mi], bl[ni]);
                }
#pragma unroll
            for (int mi = 0; mi < 2; mi++)
                ldsm4(a[mi][0], a[mi][1], a[mi][2], a[mi][3],
                      aLO + (uint32_t)(wm + mi * 16 + rA) * 256u + kA);
#pragma unroll
            for (int mi = 0; mi < 2; mi++)
#pragma unroll
                for (int ni = 0; ni < 8; ni++)
                    mma16816(c[mi][ni], a[mi], bh[ni]);
        }

        // ---- stage epilogue ------------------------------------------------
#pragma unroll
        for (int mi = 0; mi < 2; mi++) {
            int r1 = wm + mi * 16 + groupr, r2 = r1 + 8;
            int gr1 = rbase + r1, gr2 = rbase + r2;
            float rv1 = sdeg[st * TILE_M + r1], rv2 = sdeg[st * TILE_M + r2];
#pragma unroll
            for (int ni = 0; ni < 8; ni++) {
                int cc = wn + ni * 8 + qc * 2;
                float* acc = c[mi][ni];
                if (!isW2) {
                    float2 v1{acc[0] + sbias[cc], acc[1] + sbias[cc + 1]};
                    float2 v2{acc[2] + sbias[cc], acc[3] + sbias[cc + 1]};
                    if (gr1 < N_NODES) *(float2*)&out[(size_t)gr1 * D + cc] = v1;
                    if (gr2 < N_NODES) *(float2*)&out[(size_t)gr2 * D + cc] = v2;
                } else {
                    float2 v1{(acc[0] + sbias[D + cc]) * rv1,
                              (acc[1] + sbias[D + cc + 1]) * rv1};
                    float2 v2{(acc[2] + sbias[D + cc]) * rv2,
                              (acc[3] + sbias[D + cc + 1]) * rv2};
                    if (gr1 < N_NODES) *(float2*)&g_conv[(size_t)gr1 * D + cc] = v1;
                    if (gr2 < N_NODES) *(float2*)&g_conv[(size_t)gr2 * D + cc] = v2;
                }
            }
        }
        __syncthreads();   // A smem reused next stage
    }
}

// ---------------- fused aggregate + finalize + global update ----------------
// warp per node (8 nodes/warp): agg = sum conv[s]; h = relu(h1 + agg*rr) + nodes
// accumulates column sum of h into g_an; LAST block computes gnew in-place.
#define ANB 64                       // nodes per block (8 warps x 8 nodes)
#define AGG_GRID ((N_NODES + ANB - 1) / ANB)
__global__ __launch_bounds__(256)
void aggregate_kernel(const float* __restrict__ nodes,
                      const float* __restrict__ g,
                      const float* __restrict__ Wg,
                      const float* __restrict__ bg,
                      float* __restrict__ out) {
    __shared__ float scol[D];
    __shared__ int is_last;
    int tid = threadIdx.x, w = tid >> 5, lane = tid & 31;
    if (tid < D) scol[tid] = 0.f;
    __syncthreads();

    float4 col = make_float4(0.f, 0.f, 0.f, 0.f);
#pragma unroll 1
    for (int j = 0; j < 8; j++) {
        int node = blockIdx.x * ANB + w * 8 + j;
        if (node >= N_NODES) break;
        int e0 = g_rowstart[node], e1 = g_rowstart[node + 1];
        float4 acc0 = make_float4(0.f, 0.f, 0.f, 0.f);
        float4 acc1 = make_float4(0.f, 0.f, 0.f, 0.f);
        int e = e0;
        for (; e + 1 < e1; e += 2) {
            int s0 = __ldg(&g_csr[e]);
            int s1 = __ldg(&g_csr[e + 1]);
            float4 v0 = *(const float4*)&g_conv[(size_t)s0 * D + lane * 4];
            float4 v1 = *(const float4*)&g_conv[(size_t)s1 * D + lane * 4];
            acc0.x += v0.x; acc0.y += v0.y; acc0.z += v0.z; acc0.w += v0.w;
            acc1.x += v1.x; acc1.y += v1.y; acc1.z += v1.z; acc1.w += v1.w;
        }
        if (e < e1) {
            int s0 = __ldg(&g_csr[e]);
            float4 v0 = *(const float4*)&g_conv[(size_t)s0 * D + lane * 4];
            acc0.x += v0.x; acc0.y += v0.y; acc0.z += v0.z; acc0.w += v0.w;
        }
        acc0.x += acc1.x; acc0.y += acc1.y; acc0.z += acc1.z; acc0.w += acc1.w;
        float rr = rsqrtf(fmaxf((float)(e1 - e0), 1.f));
        size_t idx = (size_t)node * D + lane * 4;
        float4 h1 = *(const float4*)&out[idx];
        float4 nd = *(const float4*)&nodes[idx];
        float4 h;
        h.x = fmaxf(h1.x + acc0.x * rr, 0.f) + nd.x;
        h.y = fmaxf(h1.y + acc0.y * rr, 0.f) + nd.y;
        h.z = fmaxf(h1.z + acc0.z * rr, 0.f) + nd.z;
        h.w = fmaxf(h1.w + acc0.w * rr, 0.f) + nd.w;
        *(float4*)&out[idx] = h;
        col.x += h.x; col.y += h.y; col.z += h.z; col.w += h.w;
    }
    atomicAdd(&scol[lane * 4 + 0], col.x);
    atomicAdd(&scol[lane * 4 + 1], col.y);
    atomicAdd(&scol[lane * 4 + 2], col.z);
    atomicAdd(&scol[lane * 4 + 3], col.w);
    __syncthreads();
    if (tid < D) atomicAdd(&g_an[tid], scol[tid]);

    // ---- last block computes g_new = g + relu([an; g] @ Wg + bg) ----------
    if (tid == 0) {
        __threadfence();
        int v = atomicAdd(&g_done, 1);
        is_last = (v == AGG_GRID - 1);
    }
    __syncthreads();
    if (is_last) {
        __shared__ float sv[2 * D];
        if (tid == 0) g_done = 0;            // reset for next replay
        if (tid < D) {
            sv[tid] = g_an[tid];
            sv[D + tid] = g[tid];
        }
        __syncthreads();
        if (tid < D) {
            int c = tid;
            float acc = bg[c];
#pragma unroll 8
            for (int k = 0; k < 2 * D; k++) acc += sv[k] * Wg[k * D + c];
            out[(size_t)N_NODES * D + c] = g[c] + fmaxf(acc, 0.f);
        }
    }
}

// ---------------- launch ----------------------------------------------------
extern "C" void kernel_launch(void* const* d_in, const int* in_sizes, int n_in,
                              void* d_out, int out_size) {
    const float* nodes    = (const float*)d_in[0];
    const float* globals_ = (const float*)d_in[1];
    const int*   senders   = (const int*)d_in[2];
    const int*   receivers = (const int*)d_in[3];
    const float* W1w = (const float*)d_in[4];
    const float* W1b = (const float*)d_in[5];
    const float* W2w = (const float*)d_in[6];
    const float* W2b = (const float*)d_in[7];
    const float* W3w = (const float*)d_in[8];
    const float* W3b = (const float*)d_in[9];
    const float* Wgw = (const float*)d_in[10];
    const float* Wgb = (const float*)d_in[11];
    float* out = (float*)d_out;

    cudaFuncSetAttribute(gemm_hmma_kernel, cudaFuncAttributeMaxDynamicSharedMemorySize,
                         SM_TOTAL);

    prep_kernel<<<144 + (N_NODES + 255) / 256, 256>>>(W1w, W2w, globals_, W3w, W3b, W1b);
    degree_kernel<<<(N_EDGES + 255) / 256, 256>>>(senders, receivers);
    scan1_kernel<<<SCAN_B, 1024>>>();
    scan3_kernel<<<SCAN_B, 1024>>>();
    bucket_kernel<<<(N_EDGES + 255) / 256, 256>>>(senders, receivers);
    gemm_hmma_kernel<<<NTILES2, GT, SM_TOTAL>>>(nodes, W2b, out);
    aggregate_kernel<<<AGG_GRID, 256>>>(nodes, globals_, Wgw, Wgb, out);
}

// round 15
// speedup vs baseline: 1.1388x; 1.0665x over previous
#include <cuda_runtime.h>
#include <cuda_bf16.h>
#include <cstdint>

#define N_NODES 100000
#define N_EDGES 640000
#define D 128
#define TILE_M 128
#define CTA_M 256                       // two stages of TILE_M per CTA
#define NTILES2 ((N_NODES + CTA_M - 1) / CTA_M)
#define SCAN_B 98                       // ceil(100000/1024)

// ---------------- scratch (device globals; no dynamic allocation) ----------
__device__ float g_conv[N_NODES * D];   // (nodes@W2 + b2) * rsqrt(send_deg)
__device__ float g_gvec[D];             // globals@W3 + b3 + b1  (folded)
__device__ float g_an[D];               // column sum of h
__device__ int   g_cnt_s[N_NODES];      // send degree (int)
__device__ int   g_cnt_r[N_NODES];      // recv degree (int)
__device__ int   g_rowstart[N_NODES + 1];
__device__ int   g_cursor[N_NODES];
__device__ int   g_bsum[128];
__device__ int   g_done;                // aggregate block-completion counter
__device__ int   g_csr[N_EDGES];        // sender ids bucketed by receiver
// weight images, transposed to [n][k], bf16 hi/lo, XOR-swizzled: W1h,W1l,W2h,W2l
__device__ __align__(16) unsigned char g_Wimg[4 * 32768];

// swizzled byte offset of element (row, k) in a 128x128 bf16 image (256B rows)
__device__ __forceinline__ uint32_t swz_off(int row, int k) {
    return (uint32_t)row * 256u + (((uint32_t)k * 2u) ^ (((uint32_t)row & 7u) * 16u));
}
__device__ __forceinline__ uint32_t smem_u32(const void* p) {
    uint32_t a;
    asm("{ .reg .u64 t; cvta.to.shared.u64 t, %1; cvt.u32.u64 %0, t; }" : "=r"(a) : "l"(p));
    return a;
}
__device__ __forceinline__ void ldsm4(uint32_t& r0, uint32_t& r1, uint32_t& r2,
                                      uint32_t& r3, uint32_t addr) {
    asm volatile("ldmatrix.sync.aligned.m8n8.x4.shared.b16 {%0,%1,%2,%3}, [%4];"
                 : "=r"(r0), "=r"(r1), "=r"(r2), "=r"(r3) : "r"(addr));
}
__device__ __forceinline__ void mma16816(float* c, const uint32_t* a,
                                         const uint32_t* b) {
    asm volatile(
        "mma.sync.aligned.m16n8k16.row.col.f32.bf16.bf16.f32 "
        "{%0,%1,%2,%3}, {%4,%5,%6,%7}, {%8,%9}, {%0,%1,%2,%3};"
        : "+f"(c[0]), "+f"(c[1]), "+f"(c[2]), "+f"(c[3])
        : "r"(a[0]), "r"(a[1]), "r"(a[2]), "r"(a[3]), "r"(b[0]), "r"(b[1]));
}

// ---------------- prep: weight split + gvec (NO count zeroing here) ---------
// blocks 0..127:   weight split/transpose (W1/W2 -> bf16 hi/lo images)
// blocks 128..143: gvec (8 warps = 8 cols each) + g_an/g_done zero (block 128)
__global__ __launch_bounds__(256)
void prep_kernel(const float* __restrict__ W1, const float* __restrict__ W2,
                 const float* __restrict__ g,  const float* __restrict__ W3,
                 const float* __restrict__ b3, const float* __restrict__ b1) {
    int bx = blockIdx.x, tid = threadIdx.x;
    if (bx < 128) {
        int mat = bx & 1;                     // 0: W1, 1: W2
        int idx = (bx >> 1) * 256 + tid;      // 0..16383
        const float* W = mat ? W2 : W1;
        unsigned char* hi = g_Wimg + (size_t)(mat * 2) * 32768;
        unsigned char* lo = hi + 32768;
        int k = idx >> 7, n = idx & 127;      // coalesced read of W[k][n]
        float w = W[k * D + n];
        __nv_bfloat16 h = __float2bfloat16_rn(w);
        __nv_bfloat16 l = __float2bfloat16_rn(w - __bfloat162float(h));
        uint32_t off = swz_off(n, k);
        *(__nv_bfloat16*)(hi + off) = h;
        *(__nv_bfloat16*)(lo + off) = l;
    } else {
        if (bx == 128 && tid < D) g_an[tid] = 0.f;
        if (bx == 128 && tid == 0) g_done = 0;
        int w = tid >> 5, lane = tid & 31;
        int c = (bx - 128) * 8 + w;
        float s = 0.f;
#pragma unroll
        for (int k = lane; k < D; k += 32) s += g[k] * W3[k * D + c];
#pragma unroll
        for (int o = 16; o; o >>= 1) s += __shfl_xor_sync(0xffffffffu, s, o);
        if (lane == 0) g_gvec[c] = s + b3[c] + b1[c];
    }
}

__global__ void zerocnt_kernel() {
    int i = blockIdx.x * blockDim.x + threadIdx.x;
    if (i < N_NODES) { g_cnt_s[i] = 0; g_cnt_r[i] = 0; }
}

__global__ void degree_kernel(const int* __restrict__ senders,
                              const int* __restrict__ receivers) {
    int e = blockIdx.x * blockDim.x + threadIdx.x;
    if (e < N_EDGES) {
        atomicAdd(&g_cnt_s[senders[e]], 1);
        atomicAdd(&g_cnt_r[receivers[e]], 1);
    }
}

// ---------------- exclusive scan of recv counts -> g_rowstart ---------------
__global__ __launch_bounds__(1024) void scan1_kernel() {
    __shared__ int wsum[32];
    int t = threadIdx.x, i = blockIdx.x * 1024 + t;
    int lane = t & 31, w = t >> 5;
    int v = (i < N_NODES) ? g_cnt_r[i] : 0;
    int x = v;
#pragma unroll
    for (int off = 1; off < 32; off <<= 1) {
        int y = __shfl_up_sync(0xffffffffu, x, off);
        if (lane >= off) x += y;
    }
    if (lane == 31) wsum[w] = x;
    __syncthreads();
    if (w == 0) {
        int s = wsum[lane];
#pragma unroll
        for (int off = 1; off < 32; off <<= 1) {
            int y = __shfl_up_sync(0xffffffffu, s, off);
            if (lane >= off) s += y;
        }
        wsum[lane] = s;
    }
    __syncthreads();
    int incl = x + (w > 0 ? wsum[w - 1] : 0);
    if (i < N_NODES) g_rowstart[i] = incl - v;
    if (t == 1023) g_bsum[blockIdx.x] = incl;
}
// scan3 computes its own cross-block offset by reducing g_bsum[0..bx) in-block
__global__ __launch_bounds__(1024) void scan3_kernel() {
    __shared__ int ws[32];
    int t = threadIdx.x, bx = blockIdx.x;
    int lane = t & 31, w = t >> 5;
    int v = (t < bx) ? g_bsum[t] : 0;        // bx <= 97 so one pass suffices
#pragma unroll
    for (int o = 16; o; o >>= 1) v += __shfl_xor_sync(0xffffffffu, v, o);
    if (lane == 0) ws[w] = v;
    __syncthreads();
    if (t < 32) {
        int s = ws[t];
#pragma unroll
        for (int o = 16; o; o >>= 1) s += __shfl_xor_sync(0xffffffffu, s, o);
        if (t == 0) ws[0] = s;
    }
    __syncthreads();
    int base = ws[0];
    int i = bx * 1024 + t;
    if (i < N_NODES) {
        int val = g_rowstart[i] + base;
        g_rowstart[i] = val;
        g_cursor[i] = val;
    }
    if (i == N_NODES) g_rowstart[N_NODES] = N_EDGES;
}
__global__ void bucket_kernel(const int* __restrict__ senders,
                              const int* __restrict__ receivers) {
    int e = blockIdx.x * blockDim.x + threadIdx.x;
    if (e < N_EDGES) {
        int pos = atomicAdd(&g_cursor[receivers[e]], 1);
        g_csr[pos] = senders[e];
    }
}

// ---------------- HMMA dual GEMM (512 threads, 16 warps, 2 row-tiles) -------
#define SM_AHI  0
#define SM_ALO  32768
#define SM_W    65536                       // W1h,W1l,W2h,W2l (131072 B)
#define SM_BIAS (SM_W + 4 * 32768)          // 256 floats: gvec | b2
#define SM_DEG  (SM_BIAS + 1024)            // 256 floats (rsqrt send deg)
#define SM_TOTAL (SM_DEG + 1024)
#define GT 512

__global__ __launch_bounds__(GT, 1)
void gemm_hmma_kernel(const float* __restrict__ nodes,
                      const float* __restrict__ b2,
                      float* __restrict__ out) {
    extern __shared__ unsigned char smem[];
    uint32_t sbase = smem_u32(smem);
    int tid = threadIdx.x, wid = tid >> 5, lane = tid & 31;
    int row0 = blockIdx.x * CTA_M;
    float* sbias = (float*)(smem + SM_BIAS);
    float* sdeg  = (float*)(smem + SM_DEG);

    // ---- once-per-CTA prologue: biases, degs, weight images (plain float4)
    if (tid < D) {
        sbias[tid] = g_gvec[tid];
        sbias[D + tid] = b2[tid];
    }
    if (tid < CTA_M) {
        int gr = row0 + tid;
        sdeg[tid] = (gr < N_NODES) ? rsqrtf(fmaxf((float)g_cnt_s[gr], 1.f)) : 0.f;
    }
    {
        const float4* src = (const float4*)g_Wimg;
        float4* dst = (float4*)(smem + SM_W);
#pragma unroll
        for (int i = tid; i < (4 * 32768) / 16; i += GT) dst[i] = src[i];
    }

    // warp-constant addressing (identical math to the r9 passing kernel)
    int g = lane >> 3, i8 = lane & 7;
    int rA = i8 + 8 * (g & 1);
    int rB = i8 + 8 * (g >> 1);
    int wm = (wid & 3) * 32;
    int wc = wid >> 2;
    bool isW2 = wc >= 2;
    int wn = (wc & 1) * 64;
    uint32_t aHI = sbase + SM_AHI, aLO = sbase + SM_ALO;
    uint32_t wH = sbase + SM_W + (isW2 ? 2 : 0) * 32768;
    uint32_t wL = wH + 32768;
    uint32_t swzA = (uint32_t)i8 * 16u;
    int groupr = lane >> 2, qc = lane & 3;

#pragma unroll 1
    for (int st = 0; st < 2; st++) {
        int rbase = row0 + st * TILE_M;
        if (rbase >= N_NODES) break;
        // ---- stage A convert: fp32 -> bf16 hi/lo, swizzled ----------------
        {
            const float4* n4 = (const float4*)nodes;
#pragma unroll
            for (int i = tid; i < TILE_M * (D / 4); i += GT) {
                int r = i >> 5, q = i & 31;
                int gr = rbase + r;
                float4 v = (gr < N_NODES) ? n4[(size_t)gr * (D / 4) + q]
                                          : make_float4(0.f, 0.f, 0.f, 0.f);
                __nv_bfloat16 h0 = __float2bfloat16_rn(v.x), h1 = __float2bfloat16_rn(v.y);
                __nv_bfloat16 h2 = __float2bfloat16_rn(v.z), h3 = __float2bfloat16_rn(v.w);
                __nv_bfloat16 l0 = __float2bfloat16_rn(v.x - __bfloat162float(h0));
                __nv_bfloat16 l1 = __float2bfloat16_rn(v.y - __bfloat162float(h1));
                __nv_bfloat16 l2 = __float2bfloat16_rn(v.z - __bfloat162float(h2));
                __nv_bfloat16 l3 = __float2bfloat16_rn(v.w - __bfloat162float(h3));
                uint32_t off = (uint32_t)r * 256u +
                               (((uint32_t)q * 8u) ^ (((uint32_t)r & 7u) * 16u));
                __nv_bfloat162 ph0{h0, h1}, ph1{h2, h3}, pl0{l0, l1}, pl1{l2, l3};
                uint2 uh{*(uint32_t*)&ph0, *(uint32_t*)&ph1};
                uint2 ul{*(uint32_t*)&pl0, *(uint32_t*)&pl1};
                *(uint2*)(smem + SM_AHI + off) = uh;
                *(uint2*)(smem + SM_ALO + off) = ul;
            }
        }
        __syncthreads();

        // ---- mainloop ------------------------------------------------------
        float c[2][8][4];
#pragma unroll
        for (int mi = 0; mi < 2; mi++)
#pragma unroll
            for (int ni = 0; ni < 8; ni++)
#pragma unroll
                for (int q = 0; q < 4; q++) c[mi][ni][q] = 0.f;

#pragma unroll
        for (int ks = 0; ks < 8; ks++) {
            uint32_t kA = ((uint32_t)(ks * 32 + (g >> 1) * 16)) ^ swzA;
            uint32_t kB = ((uint32_t)(ks * 32 + (g & 1) * 16)) ^ swzA;
            uint32_t bh[8][2], bl[8][2];
#pragma unroll
            for (int nt = 0; nt < 4; nt++) {
                uint32_t rowoff = (uint32_t)(wn + nt * 16 + rB) * 256u;
                ldsm4(bh[nt * 2][0], bh[nt * 2][1], bh[nt * 2 + 1][0], bh[nt * 2 + 1][1],
                      wH + rowoff + kB);
                ldsm4(bl[nt * 2][0], bl[nt * 2][1], bl[nt * 2 + 1][0], bl[nt * 2 + 1][1],
                      wL + rowoff + kB);
            }
            uint32_t a[2][4];
#pragma unroll
            for (int mi = 0; mi < 2; mi++)
                ldsm4(a[mi][0], a[mi][1], a[mi][2], a[mi][3],
                      aHI + (uint32_t)(wm + mi * 16 + rA) * 256u + kA);
#pragma unroll
            for (int mi = 0; mi < 2; mi++)
#pragma unroll
                for (int ni = 0; ni < 8; ni++) {
                    mma16816(c[mi][ni], a[mi], bh[ni]);
                    mma16816(c[mi][ni], a[mi], bl[ni]);
                }
#pragma unroll
            for (int mi = 0; mi < 2; mi++)
                ldsm4(a[mi][0], a[mi][1], a[mi][2], a[mi][3],
                      aLO + (uint32_t)(wm + mi * 16 + rA) * 256u + kA);
#pragma unroll
            for (int mi = 0; mi < 2; mi++)
#pragma unroll
                for (int ni = 0; ni < 8; ni++)
                    mma16816(c[mi][ni], a[mi], bh[ni]);
        }

        // ---- stage epilogue ------------------------------------------------
#pragma unroll
        for (int mi = 0; mi < 2; mi++) {
            int r1 = wm + mi * 16 + groupr, r2 = r1 + 8;
            int gr1 = rbase + r1, gr2 = rbase + r2;
            float rv1 = sdeg[st * TILE_M + r1], rv2 = sdeg[st * TILE_M + r2];
#pragma unroll
            for (int ni = 0; ni < 8; ni++) {
                int cc = wn + ni * 8 + qc * 2;
                float* acc = c[mi][ni];
                if (!isW2) {
                    float2 v1{acc[0] + sbias[cc], acc[1] + sbias[cc + 1]};
                    float2 v2{acc[2] + sbias[cc], acc[3] + sbias[cc + 1]};
                    if (gr1 < N_NODES) *(float2*)&out[(size_t)gr1 * D + cc] = v1;
                    if (gr2 < N_NODES) *(float2*)&out[(size_t)gr2 * D + cc] = v2;
                } else {
                    float2 v1{(acc[0] + sbias[D + cc]) * rv1,
                              (acc[1] + sbias[D + cc + 1]) * rv1};
                    float2 v2{(acc[2] + sbias[D + cc]) * rv2,
                              (acc[3] + sbias[D + cc + 1]) * rv2};
                    if (gr1 < N_NODES) *(float2*)&g_conv[(size_t)gr1 * D + cc] = v1;
                    if (gr2 < N_NODES) *(float2*)&g_conv[(size_t)gr2 * D + cc] = v2;
                }
            }
        }
        __syncthreads();   // A smem reused next stage
    }
}

// ---------------- fused aggregate + finalize + global update ----------------
// warp per node (8 nodes/warp): agg = sum conv[s]; h = relu(h1 + agg*rr) + nodes
// accumulates column sum of h into g_an; LAST block computes gnew in-place.
#define ANB 64                       // nodes per block (8 warps x 8 nodes)
#define AGG_GRID ((N_NODES + ANB - 1) / ANB)
__global__ __launch_bounds__(256)
void aggregate_kernel(const float* __restrict__ nodes,
                      const float* __restrict__ g,
                      const float* __restrict__ Wg,
                      const float* __restrict__ bg,
                      float* __restrict__ out) {
    __shared__ float scol[D];
    __shared__ int is_last;
    int tid = threadIdx.x, w = tid >> 5, lane = tid & 31;
    if (tid < D) scol[tid] = 0.f;
    __syncthreads();

    float4 col = make_float4(0.f, 0.f, 0.f, 0.f);
#pragma unroll 1
    for (int j = 0; j < 8; j++) {
        int node = blockIdx.x * ANB + w * 8 + j;
        if (node >= N_NODES) break;
        int e0 = g_rowstart[node], e1 = g_rowstart[node + 1];
        float4 acc0 = make_float4(0.f, 0.f, 0.f, 0.f);
        float4 acc1 = make_float4(0.f, 0.f, 0.f, 0.f);
        int e = e0;
        for (; e + 1 < e1; e += 2) {
            int s0 = __ldg(&g_csr[e]);
            int s1 = __ldg(&g_csr[e + 1]);
            float4 v0 = *(const float4*)&g_conv[(size_t)s0 * D + lane * 4];
            float4 v1 = *(const float4*)&g_conv[(size_t)s1 * D + lane * 4];
            acc0.x += v0.x; acc0.y += v0.y; acc0.z += v0.z; acc0.w += v0.w;
            acc1.x += v1.x; acc1.y += v1.y; acc1.z += v1.z; acc1.w += v1.w;
        }
        if (e < e1) {
            int s0 = __ldg(&g_csr[e]);
            float4 v0 = *(const float4*)&g_conv[(size_t)s0 * D + lane * 4];
            acc0.x += v0.x; acc0.y += v0.y; acc0.z += v0.z; acc0.w += v0.w;
        }
        acc0.x += acc1.x; acc0.y += acc1.y; acc0.z += acc1.z; acc0.w += acc1.w;
        float rr = rsqrtf(fmaxf((float)(e1 - e0), 1.f));
        size_t idx = (size_t)node * D + lane * 4;
        float4 h1 = *(const float4*)&out[idx];
        float4 nd = *(const float4*)&nodes[idx];
        float4 h;
        h.x = fmaxf(h1.x + acc0.x * rr, 0.f) + nd.x;
        h.y = fmaxf(h1.y + acc0.y * rr, 0.f) + nd.y;
        h.z = fmaxf(h1.z + acc0.z * rr, 0.f) + nd.z;
        h.w = fmaxf(h1.w + acc0.w * rr, 0.f) + nd.w;
        *(float4*)&out[idx] = h;
        col.x += h.x; col.y += h.y; col.z += h.z; col.w += h.w;
    }
    atomicAdd(&scol[lane * 4 + 0], col.x);
    atomicAdd(&scol[lane * 4 + 1], col.y);
    atomicAdd(&scol[lane * 4 + 2], col.z);
    atomicAdd(&scol[lane * 4 + 3], col.w);
    __syncthreads();
    if (tid < D) atomicAdd(&g_an[tid], scol[tid]);

    // ---- last block computes g_new = g + relu([an; g] @ Wg + bg) ----------
    if (tid == 0) {
        __threadfence();
        int v = atomicAdd(&g_done, 1);
        is_last = (v == AGG_GRID - 1);
    }
    __syncthreads();
    if (is_last) {
        __shared__ float sv[2 * D];
        if (tid == 0) g_done = 0;            // reset for next replay
        if (tid < D) {
            sv[tid] = g_an[tid];
            sv[D + tid] = g[tid];
        }
        __syncthreads();
        if (tid < D) {
            int c = tid;
            float acc = bg[c];
#pragma unroll 8
            for (int k = 0; k < 2 * D; k++) acc += sv[k] * Wg[k * D + c];
            out[(size_t)N_NODES * D + c] = g[c] + fmaxf(acc, 0.f);
        }
    }
}

// ---------------- launch: fork-join capture DAG -----------------------------
extern "C" void kernel_launch(void* const* d_in, const int* in_sizes, int n_in,
                              void* d_out, int out_size) {
    const float* nodes    = (const float*)d_in[0];
    const float* globals_ = (const float*)d_in[1];
    const int*   senders   = (const int*)d_in[2];
    const int*   receivers = (const int*)d_in[3];
    const float* W1w = (const float*)d_in[4];
    const float* W1b = (const float*)d_in[5];
    const float* W2w = (const float*)d_in[6];
    const float* W2b = (const float*)d_in[7];
    const float* W3w = (const float*)d_in[8];
    const float* W3b = (const float*)d_in[9];
    const float* Wgw = (const float*)d_in[10];
    const float* Wgb = (const float*)d_in[11];
    float* out = (float*)d_out;

    cudaFuncSetAttribute(gemm_hmma_kernel, cudaFuncAttributeMaxDynamicSharedMemorySize,
                         SM_TOTAL);

    // kernel_launch runs only twice (correctness + capture); fresh stream/events
    // per call, never destroyed -> no device-memory alloc, graph sees pure DAG.
    cudaStream_t s2;
    cudaStreamCreateWithFlags(&s2, cudaStreamNonBlocking);
    cudaEvent_t e0, e1, e2;
    cudaEventCreateWithFlags(&e0, cudaEventDisableTiming);
    cudaEventCreateWithFlags(&e1, cudaEventDisableTiming);
    cudaEventCreateWithFlags(&e2, cudaEventDisableTiming);

    // fork side stream off the (captured) default stream
    cudaEventRecord(e0, 0);
    cudaStreamWaitEvent(s2, e0, 0);

    // side stream: CSR chain
    zerocnt_kernel<<<(N_NODES + 255) / 256, 256, 0, s2>>>();
    degree_kernel<<<(N_EDGES + 255) / 256, 256, 0, s2>>>(senders, receivers);
    cudaEventRecord(e1, s2);                 // GEMM needs send-counts
    scan1_kernel<<<SCAN_B, 1024, 0, s2>>>();
    scan3_kernel<<<SCAN_B, 1024, 0, s2>>>();
    bucket_kernel<<<(N_EDGES + 255) / 256, 256, 0, s2>>>(senders, receivers);
    cudaEventRecord(e2, s2);                 // aggregate needs CSR

    // main stream: weights/gvec prep overlaps zero+degree
    prep_kernel<<<144, 256>>>(W1w, W2w, globals_, W3w, W3b, W1b);
    cudaStreamWaitEvent(0, e1, 0);
    gemm_hmma_kernel<<<NTILES2, GT, SM_TOTAL>>>(nodes, W2b, out);
    cudaStreamWaitEvent(0, e2, 0);           // scan/bucket hidden under GEMM
    aggregate_kernel<<<AGG_GRID, 256>>>(nodes, globals_, Wgw, Wgb, out);
}